// round 8
// baseline (speedup 1.0000x reference)
#include <cuda_runtime.h>
#include <cuda_fp16.h>
#include <cstdint>

// ---------------------------------------------------------------------------
// QuantLinear, fp16 mma.sync (base sm_103 target — tcgen05 unavailable).
//   out[8192,11008] = x[8192,4096] @ dequant(W)[4096,11008] + bias
// Pre-pass 1: x fp32 -> fp16 scratch g_x16[m][k] (natural k order).
// Pre-pass 2: W int4 -> fp16 scratch g_w16[n][k] (transposed, natural k).
// Main: pure fp16 GEMM. 128x128x64 CTA tile, 4 warps (64x64 warp tile),
// m16n8k16, fp32 accum, ldmatrix, 3-stage cp.async pipeline for A AND B.
// ---------------------------------------------------------------------------

namespace {
constexpr int kInF  = 4096;
constexpr int kOutF = 11008;
constexpr int kM    = 8192;

constexpr int BM = 128;
constexpr int BN = 128;
constexpr int BK = 64;
constexpr int NT = kInF / BK;        // 64 k-tiles

constexpr int RSTR  = 144;           // smem row stride bytes (128B data + 16 pad)
constexpr int HALF_STAGE = 128 * RSTR;       // 18432 B (one A or B tile)
constexpr int STG   = 2 * HALF_STAGE;        // 36864 B combined A+B stage
constexpr int SMEM_TOTAL = 3 * STG;          // 110592 B (3 stages)
}  // namespace

// Static scratch (no runtime alloc): x fp16 67MB, W fp16 90MB
__device__ __align__(128) __half g_x16[(size_t)kM * kInF];
__device__ __align__(128) __half g_w16[(size_t)kOutF * kInF];

// ---------------------------------------------------------------------------
__device__ __forceinline__ uint32_t smem_u32(const void* p) {
    uint32_t a;
    asm("{ .reg .u64 t; cvta.to.shared.u64 t, %1; cvt.u32.u64 %0, t; }"
        : "=r"(a) : "l"(p));
    return a;
}

#define LDSM_X4(r0, r1, r2, r3, addr)                                          \
    asm volatile("ldmatrix.sync.aligned.m8n8.x4.shared.b16 {%0,%1,%2,%3}, [%4];" \
                 : "=r"(r0), "=r"(r1), "=r"(r2), "=r"(r3) : "r"(addr))

#define MMA16816(d, a, b0, b1)                                                \
    asm volatile(                                                             \
        "mma.sync.aligned.m16n8k16.row.col.f32.f16.f16.f32 "                  \
        "{%0,%1,%2,%3}, {%4,%5,%6,%7}, {%8,%9}, {%0,%1,%2,%3};"               \
        : "+f"((d)[0]), "+f"((d)[1]), "+f"((d)[2]), "+f"((d)[3])              \
        : "r"((a)[0]), "r"((a)[1]), "r"((a)[2]), "r"((a)[3]),                 \
          "r"(b0), "r"(b1))

#define CP_ASYNC16(dst, src)                                                  \
    asm volatile("cp.async.cg.shared.global [%0], [%1], 16;"                  \
                 :: "r"(dst), "l"(src))
#define CP_COMMIT() asm volatile("cp.async.commit_group;")
#define CP_WAIT1()  asm volatile("cp.async.wait_group 1;")

// ---------------------------------------------------------------------------
// Pre-pass 1: x fp32 -> fp16 (natural order), 8 floats / thread
// ---------------------------------------------------------------------------
__global__ void __launch_bounds__(256)
convert_x_kernel(const float* __restrict__ x) {
    size_t i = (size_t)blockIdx.x * blockDim.x + threadIdx.x;
    constexpr size_t TOT = (size_t)kM * kInF / 8;
    if (i >= TOT) return;
    const float4* s = reinterpret_cast<const float4*>(x) + i * 2;
    float4 a = s[0], b = s[1];
    __half2 h0 = __floats2half2_rn(a.x, a.y);
    __half2 h1 = __floats2half2_rn(a.z, a.w);
    __half2 h2 = __floats2half2_rn(b.x, b.y);
    __half2 h3 = __floats2half2_rn(b.z, b.w);
    uint4 o;
    o.x = *reinterpret_cast<uint32_t*>(&h0);
    o.y = *reinterpret_cast<uint32_t*>(&h1);
    o.z = *reinterpret_cast<uint32_t*>(&h2);
    o.w = *reinterpret_cast<uint32_t*>(&h3);
    reinterpret_cast<uint4*>(g_x16)[i] = o;
}

// ---------------------------------------------------------------------------
// Pre-pass 2: W int4 -> fp16, transposed to g_w16[n][k].
// Thread (n, kb8) handles 8 packed int32 (k = kb8*64 .. +64) for one n:
// reads are n-coalesced; writes are 128B contiguous per thread.
// ---------------------------------------------------------------------------
__global__ void __launch_bounds__(256)
dequant_w_kernel(const float* __restrict__ scales,
                 const int*   __restrict__ qweight,
                 const int*   __restrict__ qzeros) {
    const int n   = blockIdx.x * blockDim.x + threadIdx.x;   // 0..11007
    const int kb8 = blockIdx.y;                              // 0..63 (64 k each)
    if (n >= kOutF) return;

    const int g = kb8 >> 1;                                  // 128-k group
    const float sc = scales[(size_t)g * kOutF + n];
    const int   z  = (qzeros[(size_t)g * (kOutF / 8) + (n >> 3)] >> ((n & 7) * 4)) & 15;
    const uint32_t zbits = (0x6400u | (uint32_t)z) * 0x00010001u;
    const __half2 hz = *reinterpret_cast<const __half2*>(&zbits);
    const __half2 hs = __float2half2_rn(sc);

    const int* qp = qweight + (size_t)(kb8 * 8) * kOutF + n;
    uint4* dst = reinterpret_cast<uint4*>(g_w16 + (size_t)n * kInF + kb8 * 64);

#pragma unroll
    for (int i = 0; i < 8; ++i) {
        const uint32_t q = (uint32_t)qp[(size_t)i * kOutF];
        // adjacent-pair packing: (v0,v1) (v2,v3) (v4,v5) (v6,v7)
        uint32_t u01 = (q & 0xFu)         | ((q << 12) & 0x000F0000u) | 0x64006400u;
        uint32_t u23 = ((q >> 8) & 0xFu)  | ((q << 4)  & 0x000F0000u) | 0x64006400u;
        uint32_t u45 = ((q >> 16) & 0xFu) | ((q >> 4)  & 0x000F0000u) | 0x64006400u;
        uint32_t u67 = ((q >> 24) & 0xFu) | ((q >> 12) & 0x000F0000u) | 0x64006400u;
        __half2 v0 = __hmul2(__hsub2(*reinterpret_cast<__half2*>(&u01), hz), hs);
        __half2 v1 = __hmul2(__hsub2(*reinterpret_cast<__half2*>(&u23), hz), hs);
        __half2 v2 = __hmul2(__hsub2(*reinterpret_cast<__half2*>(&u45), hz), hs);
        __half2 v3 = __hmul2(__hsub2(*reinterpret_cast<__half2*>(&u67), hz), hs);
        uint4 pk;
        pk.x = *reinterpret_cast<uint32_t*>(&v0);
        pk.y = *reinterpret_cast<uint32_t*>(&v1);
        pk.z = *reinterpret_cast<uint32_t*>(&v2);
        pk.w = *reinterpret_cast<uint32_t*>(&v3);
        dst[i] = pk;
    }
}

// ---------------------------------------------------------------------------
// Main GEMM: 128 threads, 4 warps (2x2), 64x64 warp tiles, 3-stage cp.async
// grid: x = M tiles (64), y = N tiles (86)  -> consecutive CTAs share B stripe
// ---------------------------------------------------------------------------
__global__ void __launch_bounds__(128, 2)
qlinear_hmma_kernel(const float* __restrict__ bias,
                    float*       __restrict__ out)
{
    extern __shared__ char smem[];
    const uint32_t sb = smem_u32(smem);
    const int tid  = threadIdx.x;
    const int lane = tid & 31;
    const int wid  = tid >> 5;               // 0..3
    const int warp_m = (wid & 1) * 64;
    const int warp_n = (wid >> 1) * 64;
    const int m0 = blockIdx.x * BM;
    const int n0 = blockIdx.y * BN;

    // -------- combined A+B tile cp.async issue (tile t -> stage s) ---------
    const __half* xbase = g_x16 + (size_t)m0 * kInF;
    const __half* wbase = g_w16 + (size_t)n0 * kInF;
    auto issue_tile = [&](int t, int s) {
        const int k0 = t * BK;
#pragma unroll
        for (int j = 0; j < 8; ++j) {
            const int idx = j * 128 + tid;   // 1024 16B chunks
            const int row = idx >> 3;
            const int col = idx & 7;
            const uint32_t dA = sb + s * STG + row * RSTR + col * 16;
            CP_ASYNC16(dA, xbase + (size_t)row * kInF + k0 + col * 8);
            const uint32_t dB = dA + HALF_STAGE;
            CP_ASYNC16(dB, wbase + (size_t)row * kInF + k0 + col * 8);
        }
    };

    // -------- accumulators: 64x64 warp tile --------------------------------
    float acc[4][8][4];
#pragma unroll
    for (int mt = 0; mt < 4; ++mt)
#pragma unroll
        for (int nt = 0; nt < 8; ++nt)
#pragma unroll
            for (int r = 0; r < 4; ++r) acc[mt][nt][r] = 0.f;

    const uint32_t a_lane = (warp_m + (lane & 15)) * RSTR + (lane >> 4) * 16;
    const uint32_t b_lane = (warp_n + (lane & 7) + ((lane >> 4) << 3)) * RSTR
                          + ((lane >> 3) & 1) * 16;

    auto compute_tile = [&](int s) {
        const uint32_t abase = sb + s * STG + a_lane;
        const uint32_t bbase = sb + s * STG + HALF_STAGE + b_lane;
#pragma unroll
        for (int k16 = 0; k16 < 4; ++k16) {
            uint32_t af[4][4];
#pragma unroll
            for (int mt = 0; mt < 4; ++mt)
                LDSM_X4(af[mt][0], af[mt][1], af[mt][2], af[mt][3],
                        abase + mt * 16 * RSTR + k16 * 32);
            uint32_t bf[4][4];
#pragma unroll
            for (int nt2 = 0; nt2 < 4; ++nt2)
                LDSM_X4(bf[nt2][0], bf[nt2][1], bf[nt2][2], bf[nt2][3],
                        bbase + nt2 * 16 * RSTR + k16 * 32);
#pragma unroll
            for (int mt = 0; mt < 4; ++mt)
#pragma unroll
                for (int nt = 0; nt < 8; ++nt) {
                    const int h = (nt & 1) * 2;
                    MMA16816(acc[mt][nt], af[mt], bf[nt >> 1][h], bf[nt >> 1][h + 1]);
                }
        }
    };

    // -------- prologue: tiles 0,1 in flight --------------------------------
    issue_tile(0, 0); CP_COMMIT();
    issue_tile(1, 1); CP_COMMIT();
    CP_WAIT1();                 // tile 0 ready
    __syncthreads();

    // -------- main loop: one commit per iter keeps wait_group 1 exact ------
    int s = 0;
    for (int t = 0; t < NT; ++t) {
        if (t + 2 < NT) {
            int s2 = s + 2; if (s2 >= 3) s2 -= 3;
            issue_tile(t + 2, s2);
        }
        CP_COMMIT();
        compute_tile(s);
        if (t + 1 < NT) {
            CP_WAIT1();         // tile t+1 ready
            __syncthreads();
        }
        if (++s == 3) s = 0;
    }

    // -------- epilogue: +bias, fp32 stores ---------------------------------
    const int g  = lane >> 2;
    const int tg = lane & 3;
#pragma unroll
    for (int nt = 0; nt < 8; ++nt) {
        const int c = n0 + warp_n + nt * 8 + tg * 2;
        const float2 bv = *reinterpret_cast<const float2*>(bias + c);
#pragma unroll
        for (int mt = 0; mt < 4; ++mt) {
            const int r0 = m0 + warp_m + mt * 16 + g;
            float2 v0 = make_float2(acc[mt][nt][0] + bv.x, acc[mt][nt][1] + bv.y);
            float2 v1 = make_float2(acc[mt][nt][2] + bv.x, acc[mt][nt][3] + bv.y);
            *reinterpret_cast<float2*>(out + (size_t)r0 * kOutF + c)       = v0;
            *reinterpret_cast<float2*>(out + (size_t)(r0 + 8) * kOutF + c) = v1;
        }
    }
}

// ---------------------------------------------------------------------------
extern "C" void kernel_launch(void* const* d_in, const int* in_sizes, int n_in,
                              void* d_out, int out_size)
{
    (void)in_sizes; (void)n_in; (void)out_size;
    const float* x       = (const float*)d_in[0];
    const float* scales  = (const float*)d_in[1];
    const float* bias    = (const float*)d_in[2];
    const int*   qweight = (const int*)d_in[3];
    const int*   qzeros  = (const int*)d_in[4];
    float*       out     = (float*)d_out;

    const size_t tot8 = (size_t)kM * kInF / 8;
    convert_x_kernel<<<(unsigned)((tot8 + 255) / 256), 256>>>(x);

    dim3 wgrid((kOutF + 255) / 256, kInF / 64);   // (43, 64)
    dequant_w_kernel<<<wgrid, 256>>>(scales, qweight, qzeros);

    cudaFuncSetAttribute(qlinear_hmma_kernel,
                         cudaFuncAttributeMaxDynamicSharedMemorySize, SMEM_TOTAL);
    dim3 grid(kM / BM, kOutF / BN);  // (64, 86), M-major for B-stripe reuse
    qlinear_hmma_kernel<<<grid, 128, SMEM_TOTAL>>>(bias, out);
}

// round 9
// speedup vs baseline: 1.0113x; 1.0113x over previous
#include <cuda_runtime.h>
#include <cuda_fp16.h>
#include <cstdint>

// ---------------------------------------------------------------------------
// QuantLinear, fp16 mma.sync path (base sm_103 target — tcgen05 unavailable).
//   out[8192,11008] = x[8192,4096] @ dequant(W)[4096,11008] + bias
// Pre-pass: x fp32 -> fp16 scratch, k-permuted within 8-groups to match the
// nibble-pair dequant order [v0,v4,v1,v5,v2,v6,v3,v7].
// Main: 128x128x64 CTA tile, 4 warps (64x64 warp tile), m16n8k16 fp16 MMA,
// fp32 accum, ldmatrix, cp.async A double-buffer, B dequant INTERLEAVED into
// the MMA stream with double-buffered qweight registers (R5 + bubble removal).
// ---------------------------------------------------------------------------

namespace {
constexpr int kInF  = 4096;
constexpr int kOutF = 11008;
constexpr int kM    = 8192;

constexpr int BM = 128;
constexpr int BN = 128;
constexpr int BK = 64;
constexpr int NT = kInF / BK;        // 64 k-tiles (even)

constexpr int RSTR  = 144;           // smem row stride in bytes (128B data + 16 pad)
constexpr int STAGE = 128 * RSTR;    // 18432 B per tile stage (A or B)
constexpr int S_A   = 0;             // A stages at 0, STAGE
constexpr int S_B   = 2 * STAGE;     // B stages at 2*STAGE, 3*STAGE
constexpr int SMEM_TOTAL = 4 * STAGE;  // 73728 B
}  // namespace

// 67 MB fp16 scratch for converted x (static __device__: no runtime alloc)
__device__ __align__(128) __half g_x16[(size_t)kM * kInF];

// ---------------------------------------------------------------------------
__device__ __forceinline__ uint32_t smem_u32(const void* p) {
    uint32_t a;
    asm("{ .reg .u64 t; cvta.to.shared.u64 t, %1; cvt.u32.u64 %0, t; }"
        : "=r"(a) : "l"(p));
    return a;
}

#define LDSM_X4(r0, r1, r2, r3, addr)                                          \
    asm volatile("ldmatrix.sync.aligned.m8n8.x4.shared.b16 {%0,%1,%2,%3}, [%4];" \
                 : "=r"(r0), "=r"(r1), "=r"(r2), "=r"(r3) : "r"(addr))

#define MMA16816(d, a, b0, b1)                                                \
    asm volatile(                                                             \
        "mma.sync.aligned.m16n8k16.row.col.f32.f16.f16.f32 "                  \
        "{%0,%1,%2,%3}, {%4,%5,%6,%7}, {%8,%9}, {%0,%1,%2,%3};"               \
        : "+f"((d)[0]), "+f"((d)[1]), "+f"((d)[2]), "+f"((d)[3])              \
        : "r"((a)[0]), "r"((a)[1]), "r"((a)[2]), "r"((a)[3]),                 \
          "r"(b0), "r"(b1))

#define CP_ASYNC16(dst, src)                                                  \
    asm volatile("cp.async.cg.shared.global [%0], [%1], 16;"                  \
                 :: "r"(dst), "l"(src))
#define CP_COMMIT() asm volatile("cp.async.commit_group;")
#define CP_WAIT0()  asm volatile("cp.async.wait_group 0;")

// ---------------------------------------------------------------------------
// Pre-pass: x fp32 -> fp16, permuted within each 8-k group to
// [v0,v4,v1,v5,v2,v6,v3,v7] (matches nibble-pair dequant output order).
// ---------------------------------------------------------------------------
__global__ void __launch_bounds__(256)
convert_x_kernel(const float* __restrict__ x) {
    size_t i = (size_t)blockIdx.x * blockDim.x + threadIdx.x;  // one per 8 floats
    constexpr size_t TOT = (size_t)kM * kInF / 8;
    if (i >= TOT) return;
    const float4* s = reinterpret_cast<const float4*>(x) + i * 2;
    float4 a = s[0], b = s[1];
    __half2 h0 = __floats2half2_rn(a.x, b.x);   // (v0, v4)
    __half2 h1 = __floats2half2_rn(a.y, b.y);   // (v1, v5)
    __half2 h2 = __floats2half2_rn(a.z, b.z);   // (v2, v6)
    __half2 h3 = __floats2half2_rn(a.w, b.w);   // (v3, v7)
    uint4 o;
    o.x = *reinterpret_cast<uint32_t*>(&h0);
    o.y = *reinterpret_cast<uint32_t*>(&h1);
    o.z = *reinterpret_cast<uint32_t*>(&h2);
    o.w = *reinterpret_cast<uint32_t*>(&h3);
    reinterpret_cast<uint4*>(g_x16)[i] = o;
}

// ---------------------------------------------------------------------------
// Main GEMM kernel: 128 threads, 4 warps (2x2), 64x64 warp tiles
// ---------------------------------------------------------------------------
__global__ void __launch_bounds__(128, 2)
qlinear_hmma_kernel(const float* __restrict__ scales,
                    const float* __restrict__ bias,
                    const int*   __restrict__ qweight,
                    const int*   __restrict__ qzeros,
                    float*       __restrict__ out)
{
    extern __shared__ char smem[];
    const uint32_t sb = smem_u32(smem);
    const int tid  = threadIdx.x;
    const int lane = tid & 31;
    const int wid  = tid >> 5;               // 0..3
    const int warp_m = (wid & 1) * 64;
    const int warp_n = (wid >> 1) * 64;
    const int m0 = blockIdx.y * BM;
    const int n0 = blockIdx.x * BN;
    const int n  = n0 + tid;                 // this thread's B column

    // -------- A tile cp.async issue (tile t -> stage s) --------------------
    auto issue_a = [&](int t, int s) {
#pragma unroll
        for (int j = 0; j < 8; ++j) {
            const int idx = j * 128 + tid;   // 1024 16B chunks
            const int row = idx >> 3;
            const int col = idx & 7;
            const uint32_t dst = sb + S_A + s * STAGE + row * RSTR + col * 16;
            const __half* src = g_x16 + (size_t)(m0 + row) * kInF + t * BK + col * 8;
            CP_ASYNC16(dst, src);
        }
        CP_COMMIT();
    };

    // -------- qweight/scale/zero staging (into caller's regs) --------------
    auto ldg_qw = [&](int t, uint32_t* qw, float& sc, int& z) {
        const int* qp = qweight + (size_t)(t * 8) * kOutF + n;
#pragma unroll
        for (int i = 0; i < 8; ++i) qw[i] = (uint32_t)qp[(size_t)i * kOutF];
        const int g = t >> 1;                // 128-k group
        sc = scales[(size_t)g * kOutF + n];
        z  = (qzeros[(size_t)g * (kOutF / 8) + (n >> 3)] >> ((n & 7) * 4)) & 15;
    };

    // -------- dequant one packed int32 -> 16B smem store --------------------
    auto dq_one = [&](uint32_t q, __half2 hz, __half2 hs, char* bp, int i) {
        uint32_t u0 = (q & 0x000F000Fu)         | 0x64006400u;
        uint32_t u1 = ((q >> 4) & 0x000F000Fu)  | 0x64006400u;
        uint32_t u2 = ((q >> 8) & 0x000F000Fu)  | 0x64006400u;
        uint32_t u3 = ((q >> 12) & 0x000F000Fu) | 0x64006400u;
        __half2 v0 = __hmul2(__hsub2(*reinterpret_cast<__half2*>(&u0), hz), hs);
        __half2 v1 = __hmul2(__hsub2(*reinterpret_cast<__half2*>(&u1), hz), hs);
        __half2 v2 = __hmul2(__hsub2(*reinterpret_cast<__half2*>(&u2), hz), hs);
        __half2 v3 = __hmul2(__hsub2(*reinterpret_cast<__half2*>(&u3), hz), hs);
        uint4 pk;
        pk.x = *reinterpret_cast<uint32_t*>(&v0);
        pk.y = *reinterpret_cast<uint32_t*>(&v1);
        pk.z = *reinterpret_cast<uint32_t*>(&v2);
        pk.w = *reinterpret_cast<uint32_t*>(&v3);
        *reinterpret_cast<uint4*>(bp + i * 16) = pk;
    };

    // -------- full-tile dequant (prologue only) ----------------------------
    auto sts_b_full = [&](int s, const uint32_t* qw, float sc, int z) {
        const uint32_t zbits = (0x6400u | (uint32_t)z) * 0x00010001u;
        const __half2 hz = *reinterpret_cast<const __half2*>(&zbits);
        const __half2 hs = __float2half2_rn(sc);
        char* bp = smem + S_B + s * STAGE + tid * RSTR;
#pragma unroll
        for (int i = 0; i < 8; ++i) dq_one(qw[i], hz, hs, bp, i);
    };

    // -------- accumulators --------------------------------------------------
    float acc[4][8][4];
#pragma unroll
    for (int mt = 0; mt < 4; ++mt)
#pragma unroll
        for (int nt = 0; nt < 8; ++nt)
#pragma unroll
            for (int r = 0; r < 4; ++r) acc[mt][nt][r] = 0.f;

    // lane-dependent ldmatrix base offsets
    const uint32_t a_lane = (warp_m + (lane & 15)) * RSTR + (lane >> 4) * 16;
    const uint32_t b_lane = (warp_n + (lane & 7) + ((lane >> 4) << 3)) * RSTR
                          + ((lane >> 3) & 1) * 16;

    // compute tile in stage s; interleave dequant of next tile (stage s^1)
    auto compute_dq = [&](int s, bool do_dq, const uint32_t* qw, float sc, int z) {
        const uint32_t abase = sb + S_A + s * STAGE + a_lane;
        const uint32_t bbase = sb + S_B + s * STAGE + b_lane;
        const uint32_t zbits = (0x6400u | (uint32_t)z) * 0x00010001u;
        const __half2 hz = *reinterpret_cast<const __half2*>(&zbits);
        const __half2 hs = __float2half2_rn(sc);
        char* bp = smem + S_B + (s ^ 1) * STAGE + tid * RSTR;
#pragma unroll
        for (int k16 = 0; k16 < 4; ++k16) {
            uint32_t af[4][4];
#pragma unroll
            for (int mt = 0; mt < 4; ++mt)
                LDSM_X4(af[mt][0], af[mt][1], af[mt][2], af[mt][3],
                        abase + mt * 16 * RSTR + k16 * 32);
            uint32_t bf[4][4];
#pragma unroll
            for (int nt2 = 0; nt2 < 4; ++nt2)
                LDSM_X4(bf[nt2][0], bf[nt2][1], bf[nt2][2], bf[nt2][3],
                        bbase + nt2 * 16 * RSTR + k16 * 32);
#pragma unroll
            for (int mt = 0; mt < 4; ++mt)
#pragma unroll
                for (int nt = 0; nt < 8; ++nt) {
                    const int h = (nt & 1) * 2;
                    MMA16816(acc[mt][nt], af[mt], bf[nt >> 1][h], bf[nt >> 1][h + 1]);
                }
            // ride the idle issue slots while the tensor pipe drains
            if (do_dq) {
                dq_one(qw[2 * k16 + 0], hz, hs, bp, 2 * k16 + 0);
                dq_one(qw[2 * k16 + 1], hz, hs, bp, 2 * k16 + 1);
            }
        }
    };

    // -------- prologue ------------------------------------------------------
    uint32_t Q0[8], Q1[8];
    float sc0, sc1;
    int   z0, z1;

    issue_a(0, 0);
    ldg_qw(0, Q0, sc0, z0);
    sts_b_full(0, Q0, sc0, z0);        // B tile 0 -> stage 0
    ldg_qw(1, Q1, sc1, z1);            // qw for tile 1 (consumed at t=0)
    CP_WAIT0();                        // A(0) ready
    __syncthreads();

    // -------- main loop, unrolled x2 (qw ping-pong) -------------------------
    for (int tt = 0; tt < NT; tt += 2) {
        // ---- even iteration: t = tt; dequant tile t+1 from Q1; load t+2 -> Q0
        {
            const int t = tt;
            if (t + 1 < NT) issue_a(t + 1, (t + 1) & 1);
            if (t + 2 < NT) ldg_qw(t + 2, Q0, sc0, z0);
            compute_dq(t & 1, t + 1 < NT, Q1, sc1, z1);
            if (t + 1 < NT) { CP_WAIT0(); __syncthreads(); }
        }
        // ---- odd iteration: t = tt+1; dequant tile t+1 from Q0; load t+2 -> Q1
        {
            const int t = tt + 1;
            if (t + 1 < NT) issue_a(t + 1, (t + 1) & 1);
            if (t + 2 < NT) ldg_qw(t + 2, Q1, sc1, z1);
            compute_dq(t & 1, t + 1 < NT, Q0, sc0, z0);
            if (t + 1 < NT) { CP_WAIT0(); __syncthreads(); }
        }
    }

    // -------- epilogue: +bias, fp32 stores ---------------------------------
    const int g  = lane >> 2;
    const int tg = lane & 3;
#pragma unroll
    for (int nt = 0; nt < 8; ++nt) {
        const int c = n0 + warp_n + nt * 8 + tg * 2;
        const float2 bv = *reinterpret_cast<const float2*>(bias + c);
#pragma unroll
        for (int mt = 0; mt < 4; ++mt) {
            const int r0 = m0 + warp_m + mt * 16 + g;
            float2 v0 = make_float2(acc[mt][nt][0] + bv.x, acc[mt][nt][1] + bv.y);
            float2 v1 = make_float2(acc[mt][nt][2] + bv.x, acc[mt][nt][3] + bv.y);
            *reinterpret_cast<float2*>(out + (size_t)r0 * kOutF + c)       = v0;
            *reinterpret_cast<float2*>(out + (size_t)(r0 + 8) * kOutF + c) = v1;
        }
    }
}

// ---------------------------------------------------------------------------
extern "C" void kernel_launch(void* const* d_in, const int* in_sizes, int n_in,
                              void* d_out, int out_size)
{
    (void)in_sizes; (void)n_in; (void)out_size;
    const float* x       = (const float*)d_in[0];
    const float* scales  = (const float*)d_in[1];
    const float* bias    = (const float*)d_in[2];
    const int*   qweight = (const int*)d_in[3];
    const int*   qzeros  = (const int*)d_in[4];
    float*       out     = (float*)d_out;

    const size_t tot8 = (size_t)kM * kInF / 8;
    convert_x_kernel<<<(unsigned)((tot8 + 255) / 256), 256>>>(x);

    cudaFuncSetAttribute(qlinear_hmma_kernel,
                         cudaFuncAttributeMaxDynamicSharedMemorySize, SMEM_TOTAL);
    dim3 grid(kOutF / BN, kM / BM);  // (86, 64)
    qlinear_hmma_kernel<<<grid, 128, SMEM_TOTAL>>>(scales, bias, qweight, qzeros, out);
}